// round 4
// baseline (speedup 1.0000x reference)
#include <cuda_runtime.h>
#include <cuda_fp16.h>
#include <cstdint>

// ---------------------------------------------------------------------------
// Problem constants
// ---------------------------------------------------------------------------
#define M_TOTAL 8192
#define N_TOTAL 4096
#define K_TOTAL 4096

#define TILE_M 256
#define TILE_N 128
#define TILE_K 64                    // K per pipeline stage
#define KTILES (K_TOTAL / TILE_K)    // 64
#define STAGES 4
#define THREADS 512
#define N_TILES (N_TOTAL / TILE_N)   // 32
#define M_TILES (M_TOTAL / TILE_M)   // 32
#define GROUP_M 8

#define STAGE_ROWS (TILE_M + TILE_N)            // 384 rows x 128B
#define STAGE_BYTES (STAGE_ROWS * 128)          // 48KB
#define SMEM_DYN (STAGES * STAGE_BYTES)         // 192KB

// ---------------------------------------------------------------------------
// Scratch: pre-converted fp16 operands (device globals -> no allocations)
// ---------------------------------------------------------------------------
__device__ __half g_xh[(size_t)M_TOTAL * K_TOTAL];   // 67 MB
__device__ __half g_wh[(size_t)N_TOTAL * K_TOTAL];   // 33.5 MB

// ---------------------------------------------------------------------------
// Helpers
// ---------------------------------------------------------------------------
__device__ __forceinline__ uint32_t smem_u32(const void* p) {
    uint32_t a;
    asm("{ .reg .u64 t; cvta.to.shared.u64 t, %1; cvt.u32.u64 %0, t; }"
        : "=r"(a) : "l"(p));
    return a;
}

__device__ __forceinline__ uint32_t sw128(uint32_t off) {
    return off ^ ((off >> 3) & 0x70);
}

__device__ __forceinline__ void cp_async16(uint32_t dst, const void* src) {
    asm volatile("cp.async.cg.shared.global [%0], [%1], 16;"
                 :: "r"(dst), "l"(src) : "memory");
}
__device__ __forceinline__ void cp_commit() {
    asm volatile("cp.async.commit_group;" ::: "memory");
}
template <int N>
__device__ __forceinline__ void cp_wait() {
    asm volatile("cp.async.wait_group %0;" :: "n"(N) : "memory");
}

__device__ __forceinline__ void ldsm_x4(uint32_t& r0, uint32_t& r1, uint32_t& r2,
                                        uint32_t& r3, uint32_t addr) {
    asm volatile("ldmatrix.sync.aligned.m8n8.x4.shared.b16 {%0,%1,%2,%3}, [%4];"
                 : "=r"(r0), "=r"(r1), "=r"(r2), "=r"(r3) : "r"(addr));
}

__device__ __forceinline__ void mma16816(float& c0, float& c1, float& c2, float& c3,
                                         uint32_t a0, uint32_t a1, uint32_t a2,
                                         uint32_t a3, uint32_t b0, uint32_t b1) {
    asm volatile(
        "mma.sync.aligned.m16n8k16.row.col.f32.f16.f16.f32 "
        "{%0,%1,%2,%3}, {%4,%5,%6,%7}, {%8,%9}, {%0,%1,%2,%3};"
        : "+f"(c0), "+f"(c1), "+f"(c2), "+f"(c3)
        : "r"(a0), "r"(a1), "r"(a2), "r"(a3), "r"(b0), "r"(b1));
}

// ---------------------------------------------------------------------------
// Pass 1a: convert X (fp32) -> fp16
// ---------------------------------------------------------------------------
__global__ void __launch_bounds__(256) cvt_x_kernel(const float* __restrict__ x) {
    size_t i = (size_t)blockIdx.x * blockDim.x + threadIdx.x;   // chunk of 8 floats
    size_t n8 = (size_t)M_TOTAL * K_TOTAL / 8;
    if (i >= n8) return;
    const float4* s = reinterpret_cast<const float4*>(x) + 2 * i;
    float4 a = s[0], b = s[1];
    __half2 h0 = __floats2half2_rn(a.x, a.y);
    __half2 h1 = __floats2half2_rn(a.z, a.w);
    __half2 h2 = __floats2half2_rn(b.x, b.y);
    __half2 h3 = __floats2half2_rn(b.z, b.w);
    uint4 o;
    o.x = reinterpret_cast<uint32_t&>(h0);
    o.y = reinterpret_cast<uint32_t&>(h1);
    o.z = reinterpret_cast<uint32_t&>(h2);
    o.w = reinterpret_cast<uint32_t&>(h3);
    reinterpret_cast<uint4*>(g_xh)[i] = o;
}

// ---------------------------------------------------------------------------
// Pass 1b: dequantize W (int32 q * per-64-block scale) -> fp16
// flat element e has block id e/64; a chunk of 8 stays inside one block.
// ---------------------------------------------------------------------------
__global__ void __launch_bounds__(256) cvt_w_kernel(const int* __restrict__ qw,
                                                    const float* __restrict__ scales) {
    size_t i = (size_t)blockIdx.x * blockDim.x + threadIdx.x;   // chunk of 8 ints
    size_t n8 = (size_t)N_TOTAL * K_TOTAL / 8;
    if (i >= n8) return;
    float sc = __ldg(scales + (i >> 3));
    const int4* s = reinterpret_cast<const int4*>(qw) + 2 * i;
    int4 q0 = s[0], q1 = s[1];
    __half2 h0 = __floats2half2_rn((float)q0.x * sc, (float)q0.y * sc);
    __half2 h1 = __floats2half2_rn((float)q0.z * sc, (float)q0.w * sc);
    __half2 h2 = __floats2half2_rn((float)q1.x * sc, (float)q1.y * sc);
    __half2 h3 = __floats2half2_rn((float)q1.z * sc, (float)q1.w * sc);
    uint4 o;
    o.x = reinterpret_cast<uint32_t&>(h0);
    o.y = reinterpret_cast<uint32_t&>(h1);
    o.z = reinterpret_cast<uint32_t&>(h2);
    o.w = reinterpret_cast<uint32_t&>(h3);
    reinterpret_cast<uint4*>(g_wh)[i] = o;
}

// ---------------------------------------------------------------------------
// Pass 2: HMMA GEMM, 256x128 CTA tile, 16 warps (warp tile 64x32),
//         4-stage cp.async pipeline, single barrier per ktile.
//   A = g_xh [M,K] K-major, B = g_wh [N,K] K-major (TN).
// ---------------------------------------------------------------------------
__global__ void __launch_bounds__(THREADS, 1) gemm_kernel(const float* __restrict__ bias,
                                                          float* __restrict__ out) {
    extern __shared__ char smem[];
    uint32_t sb = smem_u32(smem);

    int tid = threadIdx.x;
    int wid = tid >> 5;
    int lane = tid & 31;
    int warp_m = wid & 3;        // 4 warps in M (64 rows each)
    int warp_n = wid >> 2;       // 4 warps in N (32 cols each)

    // grouped tile rasterization for L2 reuse
    int bid = blockIdx.x;
    int group = bid / (GROUP_M * N_TILES);
    int rem = bid % (GROUP_M * N_TILES);
    int m_tile = group * GROUP_M + (rem % GROUP_M);
    int n_tile = rem / GROUP_M;
    int m_base = m_tile * TILE_M;
    int n_base = n_tile * TILE_N;

    const __half* Abase = g_xh + (size_t)m_base * K_TOTAL;
    const __half* Bbase = g_wh + (size_t)n_base * K_TOTAL;

    // cp.async per-thread coords: chunk = 16B; stage = 384 rows x 8 chunks.
    // 512 threads -> 6 chunks each: 4 A row-groups (64 rows apart), 2 B.
    int tr = tid >> 3;                 // 0..63
    int tc8 = (tid & 7) * 8;           // fp16 col offset
    // swizzle pattern repeats every 1024B; +64 rows = +8192B keeps it invariant
    uint32_t s0 = sw128((uint32_t)(tr * 128 + (tid & 7) * 16));

    float acc[4][4][4];
#pragma unroll
    for (int mi = 0; mi < 4; ++mi)
#pragma unroll
        for (int ni = 0; ni < 4; ++ni)
#pragma unroll
            for (int e = 0; e < 4; ++e) acc[mi][ni][e] = 0.0f;

    auto load_stage = [&](int kt, int buf) {
        uint32_t stage_base = sb + buf * STAGE_BYTES;
        const __half* Ak = Abase + kt * TILE_K;
        const __half* Bk = Bbase + kt * TILE_K;
#pragma unroll
        for (int i = 0; i < 4; ++i) {   // A: 256 rows (4 groups of 64)
            cp_async16(stage_base + s0 + (uint32_t)i * 8192,
                       Ak + (size_t)(64 * i + tr) * K_TOTAL + tc8);
        }
        uint32_t bsm = stage_base + TILE_M * 128;
#pragma unroll
        for (int i = 0; i < 2; ++i) {   // B: 128 rows (2 groups of 64)
            cp_async16(bsm + s0 + (uint32_t)i * 8192,
                       Bk + (size_t)(64 * i + tr) * K_TOTAL + tc8);
        }
        cp_commit();
    };

    // prologue
    load_stage(0, 0);
    load_stage(1, 1);
    load_stage(2, 2);

    int lrow = lane & 15;        // row within 16-row block
    int lhalf = lane >> 4;       // which 8-col (k) half

    for (int kt = 0; kt < KTILES; ++kt) {
        cp_wait<2>();
        __syncthreads();
        // single barrier per ktile: per-warp program order puts kt-1 MMAs
        // before this barrier, so overwriting buffer (kt+3)&3 == (kt-1)&3
        // below is safe.
        if (kt + 3 < KTILES) load_stage(kt + 3, (kt + 3) & (STAGES - 1));

        int buf = kt & (STAGES - 1);
        uint32_t abase = sb + buf * STAGE_BYTES;
        uint32_t bbase = abase + TILE_M * 128;

#pragma unroll
        for (int ks = 0; ks < 4; ++ks) {        // 4 x k16 per stage
            uint32_t a0[4], a1[4], a2[4], a3[4];
#pragma unroll
            for (int mi = 0; mi < 4; ++mi) {
                int row = warp_m * 64 + mi * 16 + lrow;
                uint32_t off = (uint32_t)(row * 128 + ks * 32 + lhalf * 16);
                ldsm_x4(a0[mi], a1[mi], a2[mi], a3[mi], abase + sw128(off));
            }
            uint32_t b0[4], b1[4];
#pragma unroll
            for (int nh = 0; nh < 2; ++nh) {
                int row = warp_n * 32 + nh * 16 + lrow;
                uint32_t off = (uint32_t)(row * 128 + ks * 32 + lhalf * 16);
                uint32_t r0, r1, r2, r3;
                ldsm_x4(r0, r1, r2, r3, bbase + sw128(off));
                b0[nh * 2 + 0] = r0; b1[nh * 2 + 0] = r2;
                b0[nh * 2 + 1] = r1; b1[nh * 2 + 1] = r3;
            }
#pragma unroll
            for (int mi = 0; mi < 4; ++mi)
#pragma unroll
                for (int ni = 0; ni < 4; ++ni)
                    mma16816(acc[mi][ni][0], acc[mi][ni][1],
                             acc[mi][ni][2], acc[mi][ni][3],
                             a0[mi], a1[mi], a2[mi], a3[mi],
                             b0[ni], b1[ni]);
        }
    }

    // epilogue: bias add + store
    int qr = lane >> 2;          // 0..7
    int qc = (lane & 3) * 2;     // 0,2,4,6
#pragma unroll
    for (int mi = 0; mi < 4; ++mi) {
        int row0 = m_base + warp_m * 64 + mi * 16 + qr;
#pragma unroll
        for (int ni = 0; ni < 4; ++ni) {
            int col = n_base + warp_n * 32 + ni * 8 + qc;
            float bx = __ldg(bias + col);
            float by = __ldg(bias + col + 1);
            float2 v0 = make_float2(acc[mi][ni][0] + bx, acc[mi][ni][1] + by);
            float2 v1 = make_float2(acc[mi][ni][2] + bx, acc[mi][ni][3] + by);
            *reinterpret_cast<float2*>(out + (size_t)row0 * N_TOTAL + col) = v0;
            *reinterpret_cast<float2*>(out + (size_t)(row0 + 8) * N_TOTAL + col) = v1;
        }
    }
}

// ---------------------------------------------------------------------------
// kernel_launch
// ---------------------------------------------------------------------------
extern "C" void kernel_launch(void* const* d_in, const int* in_sizes, int n_in,
                              void* d_out, int out_size) {
    const float* x      = (const float*)d_in[0];
    const int*   qw     = (const int*)d_in[1];
    const float* scales = (const float*)d_in[2];
    const float* bias   = (const float*)d_in[3];
    float*       out    = (float*)d_out;

    cudaFuncSetAttribute(gemm_kernel, cudaFuncAttributeMaxDynamicSharedMemorySize, SMEM_DYN);

    int n8x = (int)((size_t)M_TOTAL * K_TOTAL / 8);   // 4,194,304
    int n8w = (int)((size_t)N_TOTAL * K_TOTAL / 8);   // 2,097,152
    cvt_x_kernel<<<(n8x + 255) / 256, 256>>>(x);
    cvt_w_kernel<<<(n8w + 255) / 256, 256>>>(qw, scales);
    gemm_kernel<<<M_TILES * N_TILES, THREADS, SMEM_DYN>>>(bias, out);
}

// round 5
// speedup vs baseline: 1.0762x; 1.0762x over previous
#include <cuda_runtime.h>
#include <cuda_fp16.h>
#include <cstdint>

// ---------------------------------------------------------------------------
// Problem constants
// ---------------------------------------------------------------------------
#define M_TOTAL 8192
#define N_TOTAL 4096
#define K_TOTAL 4096

#define TILE_M 256
#define TILE_N 128
#define TILE_K 64                    // K per pipeline stage
#define KTILES (K_TOTAL / TILE_K)    // 64
#define STAGES 4
#define THREADS 512
#define N_TILES (N_TOTAL / TILE_N)   // 32
#define M_TILES (M_TOTAL / TILE_M)   // 32
#define GROUP_M 8

#define A_BLK_BYTES (TILE_M * 128)              // 32KB per (m_tile, ktile)
#define B_BLK_BYTES (TILE_N * 128)              // 16KB per (n_tile, ktile)
#define STAGE_BYTES (A_BLK_BYTES + B_BLK_BYTES) // 48KB
#define SMEM_DYN (STAGES * STAGE_BYTES)         // 192KB

// ---------------------------------------------------------------------------
// Scratch: pre-converted fp16 operands, TILE-MAJOR + PRE-SWIZZLED.
//   g_xh: [m_tile(32)][ktile(64)] blocks of 256rows x 64k fp16 (32KB),
//         within-block byte off stored at sw128(r*128 + k*2).
//   g_wh: [n_tile(32)][ktile(64)] blocks of 128rows x 64k fp16 (16KB), same.
// ---------------------------------------------------------------------------
__device__ __half g_xh[(size_t)M_TOTAL * K_TOTAL];   // 67 MB
__device__ __half g_wh[(size_t)N_TOTAL * K_TOTAL];   // 33.5 MB

// ---------------------------------------------------------------------------
// Helpers
// ---------------------------------------------------------------------------
__device__ __forceinline__ uint32_t smem_u32(const void* p) {
    uint32_t a;
    asm("{ .reg .u64 t; cvta.to.shared.u64 t, %1; cvt.u32.u64 %0, t; }"
        : "=r"(a) : "l"(p));
    return a;
}

__device__ __forceinline__ uint32_t sw128(uint32_t off) {
    return off ^ ((off >> 3) & 0x70);
}

__device__ __forceinline__ void mbar_init(uint32_t mbar, uint32_t cnt) {
    asm volatile("mbarrier.init.shared::cta.b64 [%0], %1;"
                 :: "r"(mbar), "r"(cnt) : "memory");
}

__device__ __forceinline__ void mbar_expect_tx(uint32_t mbar, uint32_t tx) {
    asm volatile("mbarrier.arrive.expect_tx.shared::cta.b64 _, [%0], %1;"
                 :: "r"(mbar), "r"(tx) : "memory");
}

__device__ __forceinline__ void mbar_wait(uint32_t mbar, uint32_t parity) {
    asm volatile(
        "{\n\t"
        ".reg .pred P;\n\t"
        "WAIT_%=:\n\t"
        "mbarrier.try_wait.parity.acquire.cta.shared::cta.b64 P, [%0], %1, 0x989680;\n\t"
        "@P bra.uni DONE_%=;\n\t"
        "bra.uni WAIT_%=;\n\t"
        "DONE_%=:\n\t"
        "}"
        :: "r"(mbar), "r"(parity) : "memory");
}

__device__ __forceinline__ void bulk_ld(uint32_t dst_smem, const void* src,
                                        uint32_t bytes, uint32_t mbar) {
    asm volatile(
        "cp.async.bulk.shared::cluster.global.mbarrier::complete_tx::bytes "
        "[%0], [%1], %2, [%3];"
        :: "r"(dst_smem), "l"(src), "r"(bytes), "r"(mbar) : "memory");
}

__device__ __forceinline__ void ldsm_x4(uint32_t& r0, uint32_t& r1, uint32_t& r2,
                                        uint32_t& r3, uint32_t addr) {
    asm volatile("ldmatrix.sync.aligned.m8n8.x4.shared.b16 {%0,%1,%2,%3}, [%4];"
                 : "=r"(r0), "=r"(r1), "=r"(r2), "=r"(r3) : "r"(addr));
}

__device__ __forceinline__ void mma16816(float& c0, float& c1, float& c2, float& c3,
                                         uint32_t a0, uint32_t a1, uint32_t a2,
                                         uint32_t a3, uint32_t b0, uint32_t b1) {
    asm volatile(
        "mma.sync.aligned.m16n8k16.row.col.f32.f16.f16.f32 "
        "{%0,%1,%2,%3}, {%4,%5,%6,%7}, {%8,%9}, {%0,%1,%2,%3};"
        : "+f"(c0), "+f"(c1), "+f"(c2), "+f"(c3)
        : "r"(a0), "r"(a1), "r"(a2), "r"(a3), "r"(b0), "r"(b1));
}

// ---------------------------------------------------------------------------
// Pass 1a: convert X (fp32) -> fp16, tile-major pre-swizzled layout.
// Destination is written linearly (chunk i -> byte i*16); source coords are
// recovered via the sw128 involution.
// ---------------------------------------------------------------------------
__global__ void __launch_bounds__(256) cvt_x_kernel(const float* __restrict__ x) {
    size_t i = (size_t)blockIdx.x * blockDim.x + threadIdx.x;   // dst 16B chunk
    size_t n8 = (size_t)M_TOTAL * K_TOTAL / 8;
    if (i >= n8) return;
    uint32_t blk = (uint32_t)(i >> 11);          // 2048 chunks per 32KB block
    uint32_t w = (uint32_t)(i & 2047);
    uint32_t mt = blk >> 6;                      // m_tile
    uint32_t kt = blk & 63;                      // ktile
    uint32_t src_off = sw128(w * 16);            // logical byte off in block
    uint32_t r = src_off >> 7;                   // row 0..255
    uint32_t kc = (src_off & 127) >> 1;          // k within tile 0..63 (chunk start)
    size_t m = (size_t)mt * TILE_M + r;
    size_t k = (size_t)kt * TILE_K + kc;
    const float4* s = reinterpret_cast<const float4*>(x + m * K_TOTAL + k);
    float4 a = s[0], b = s[1];
    __half2 h0 = __floats2half2_rn(a.x, a.y);
    __half2 h1 = __floats2half2_rn(a.z, a.w);
    __half2 h2 = __floats2half2_rn(b.x, b.y);
    __half2 h3 = __floats2half2_rn(b.z, b.w);
    uint4 o;
    o.x = reinterpret_cast<uint32_t&>(h0);
    o.y = reinterpret_cast<uint32_t&>(h1);
    o.z = reinterpret_cast<uint32_t&>(h2);
    o.w = reinterpret_cast<uint32_t&>(h3);
    reinterpret_cast<uint4*>(g_xh)[i] = o;
}

// ---------------------------------------------------------------------------
// Pass 1b: dequantize W -> fp16, tile-major pre-swizzled layout.
// flat element e = n*4096+k has scale block e/64 = n*64 + kt (8-chunk stays
// inside one block).
// ---------------------------------------------------------------------------
__global__ void __launch_bounds__(256) cvt_w_kernel(const int* __restrict__ qw,
                                                    const float* __restrict__ scales) {
    size_t i = (size_t)blockIdx.x * blockDim.x + threadIdx.x;   // dst 16B chunk
    size_t n8 = (size_t)N_TOTAL * K_TOTAL / 8;
    if (i >= n8) return;
    uint32_t blk = (uint32_t)(i >> 10);          // 1024 chunks per 16KB block
    uint32_t w = (uint32_t)(i & 1023);
    uint32_t nt = blk >> 6;                      // n_tile
    uint32_t kt = blk & 63;                      // ktile
    uint32_t src_off = sw128(w * 16);
    uint32_t r = src_off >> 7;                   // row 0..127
    uint32_t kc = (src_off & 127) >> 1;          // k within tile
    size_t n = (size_t)nt * TILE_N + r;
    size_t k = (size_t)kt * TILE_K + kc;
    float sc = __ldg(scales + (n * 64 + kt));
    const int4* s = reinterpret_cast<const int4*>(qw + n * K_TOTAL + k);
    int4 q0 = s[0], q1 = s[1];
    __half2 h0 = __floats2half2_rn((float)q0.x * sc, (float)q0.y * sc);
    __half2 h1 = __floats2half2_rn((float)q0.z * sc, (float)q0.w * sc);
    __half2 h2 = __floats2half2_rn((float)q1.x * sc, (float)q1.y * sc);
    __half2 h3 = __floats2half2_rn((float)q1.z * sc, (float)q1.w * sc);
    uint4 o;
    o.x = reinterpret_cast<uint32_t&>(h0);
    o.y = reinterpret_cast<uint32_t&>(h1);
    o.z = reinterpret_cast<uint32_t&>(h2);
    o.w = reinterpret_cast<uint32_t&>(h3);
    reinterpret_cast<uint4*>(g_wh)[i] = o;
}

// ---------------------------------------------------------------------------
// Pass 2: HMMA GEMM, 256x128 CTA tile, 16 warps (warp tile 64x32),
//         4-stage pipeline fed by cp.async.bulk (TMA) + mbarrier.
// ---------------------------------------------------------------------------
__global__ void __launch_bounds__(THREADS, 1) gemm_kernel(const float* __restrict__ bias,
                                                          float* __restrict__ out) {
    extern __shared__ __align__(1024) char smem[];
    __shared__ __align__(8) uint64_t mbars[STAGES];
    uint32_t sb = smem_u32(smem);
    uint32_t mb = smem_u32(mbars);

    int tid = threadIdx.x;
    int wid = tid >> 5;
    int lane = tid & 31;
    int warp_m = wid & 3;        // 4 warps in M (64 rows each)
    int warp_n = wid >> 2;       // 4 warps in N (32 cols each)

    // grouped tile rasterization for L2 reuse
    int bid = blockIdx.x;
    int group = bid / (GROUP_M * N_TILES);
    int rem = bid % (GROUP_M * N_TILES);
    int m_tile = group * GROUP_M + (rem % GROUP_M);
    int n_tile = rem / GROUP_M;

    const char* Ablk = reinterpret_cast<const char*>(g_xh) +
                       (size_t)(m_tile * KTILES) * A_BLK_BYTES;
    const char* Bblk = reinterpret_cast<const char*>(g_wh) +
                       (size_t)(n_tile * KTILES) * B_BLK_BYTES;

    if (tid == 0) {
#pragma unroll
        for (int s = 0; s < STAGES; ++s) mbar_init(mb + 8 * s, 1);
    }
    __syncthreads();

    auto load_stage = [&](int kt, int buf) {
        // single issuer
        uint32_t m = mb + 8 * buf;
        mbar_expect_tx(m, STAGE_BYTES);
        uint32_t stage_base = sb + buf * STAGE_BYTES;
        bulk_ld(stage_base, Ablk + (size_t)kt * A_BLK_BYTES, A_BLK_BYTES, m);
        bulk_ld(stage_base + A_BLK_BYTES, Bblk + (size_t)kt * B_BLK_BYTES,
                B_BLK_BYTES, m);
    };

    // prologue: stages 0..2 (issued by one thread)
    if (tid == 0) {
        load_stage(0, 0);
        load_stage(1, 1);
        load_stage(2, 2);
    }

    float acc[4][4][4];
#pragma unroll
    for (int mi = 0; mi < 4; ++mi)
#pragma unroll
        for (int ni = 0; ni < 4; ++ni)
#pragma unroll
            for (int e = 0; e < 4; ++e) acc[mi][ni][e] = 0.0f;

    int lrow = lane & 15;        // row within 16-row block
    int lhalf = lane >> 4;       // which 8-col (k) half

    for (int kt = 0; kt < KTILES; ++kt) {
        int buf = kt & (STAGES - 1);
        // barrier first: guarantees all warps finished reading buffer
        // (kt+3)&3 == (kt-1)&3 before tid0 re-targets it with TMA.
        __syncthreads();
        if (tid == 0 && kt + 3 < KTILES) load_stage(kt + 3, (kt + 3) & (STAGES - 1));

        // wait for this stage's TMA completion; use index = kt>>2, parity alternates
        mbar_wait(mb + 8 * buf, (kt >> 2) & 1);

        uint32_t abase = sb + buf * STAGE_BYTES;
        uint32_t bbase = abase + A_BLK_BYTES;

#pragma unroll
        for (int ks = 0; ks < 4; ++ks) {        // 4 x k16 per stage
            uint32_t a0[4], a1[4], a2[4], a3[4];
#pragma unroll
            for (int mi = 0; mi < 4; ++mi) {
                int row = warp_m * 64 + mi * 16 + lrow;
                uint32_t off = (uint32_t)(row * 128 + ks * 32 + lhalf * 16);
                ldsm_x4(a0[mi], a1[mi], a2[mi], a3[mi], abase + sw128(off));
            }
            uint32_t b0[4], b1[4];
#pragma unroll
            for (int nh = 0; nh < 2; ++nh) {
                int row = warp_n * 32 + nh * 16 + lrow;
                uint32_t off = (uint32_t)(row * 128 + ks * 32 + lhalf * 16);
                uint32_t r0, r1, r2, r3;
                ldsm_x4(r0, r1, r2, r3, bbase + sw128(off));
                b0[nh * 2 + 0] = r0; b1[nh * 2 + 0] = r2;
                b0[nh * 2 + 1] = r1; b1[nh * 2 + 1] = r3;
            }
#pragma unroll
            for (int mi = 0; mi < 4; ++mi)
#pragma unroll
                for (int ni = 0; ni < 4; ++ni)
                    mma16816(acc[mi][ni][0], acc[mi][ni][1],
                             acc[mi][ni][2], acc[mi][ni][3],
                             a0[mi], a1[mi], a2[mi], a3[mi],
                             b0[ni], b1[ni]);
        }
    }

    // epilogue: bias add + store
    int m_base = m_tile * TILE_M;
    int n_base = n_tile * TILE_N;
    int qr = lane >> 2;          // 0..7
    int qc = (lane & 3) * 2;     // 0,2,4,6
#pragma unroll
    for (int mi = 0; mi < 4; ++mi) {
        int row0 = m_base + warp_m * 64 + mi * 16 + qr;
#pragma unroll
        for (int ni = 0; ni < 4; ++ni) {
            int col = n_base + warp_n * 32 + ni * 8 + qc;
            float bx = __ldg(bias + col);
            float by = __ldg(bias + col + 1);
            float2 v0 = make_float2(acc[mi][ni][0] + bx, acc[mi][ni][1] + by);
            float2 v1 = make_float2(acc[mi][ni][2] + bx, acc[mi][ni][3] + by);
            *reinterpret_cast<float2*>(out + (size_t)row0 * N_TOTAL + col) = v0;
            *reinterpret_cast<float2*>(out + (size_t)(row0 + 8) * N_TOTAL + col) = v1;
        }
    }
}

// ---------------------------------------------------------------------------
// kernel_launch
// ---------------------------------------------------------------------------
extern "C" void kernel_launch(void* const* d_in, const int* in_sizes, int n_in,
                              void* d_out, int out_size) {
    const float* x      = (const float*)d_in[0];
    const int*   qw     = (const int*)d_in[1];
    const float* scales = (const float*)d_in[2];
    const float* bias   = (const float*)d_in[3];
    float*       out    = (float*)d_out;

    cudaFuncSetAttribute(gemm_kernel, cudaFuncAttributeMaxDynamicSharedMemorySize, SMEM_DYN);

    int n8x = (int)((size_t)M_TOTAL * K_TOTAL / 8);   // 4,194,304
    int n8w = (int)((size_t)N_TOTAL * K_TOTAL / 8);   // 2,097,152
    cvt_x_kernel<<<(n8x + 255) / 256, 256>>>(x);
    cvt_w_kernel<<<(n8w + 255) / 256, 256>>>(qw, scales);
    gemm_kernel<<<M_TILES * N_TILES, THREADS, SMEM_DYN>>>(bias, out);
}

// round 6
// speedup vs baseline: 1.0789x; 1.0025x over previous
#include <cuda_runtime.h>
#include <cuda_fp16.h>
#include <cstdint>

// ---------------------------------------------------------------------------
// Problem constants
// ---------------------------------------------------------------------------
#define M_TOTAL 8192
#define N_TOTAL 4096
#define K_TOTAL 4096

#define TILE_M 256
#define TILE_N 128
#define KB64 64                      // granularity of pre-packed blocks
#define KTILES64 (K_TOTAL / KB64)    // 64 blocks in K
#define ITERS (KTILES64 / 2)         // 32 mainloop iterations (K=128 each)
#define STAGES 2
#define THREADS 512
#define N_TILES (N_TOTAL / TILE_N)   // 32
#define M_TILES (M_TOTAL / TILE_M)   // 32
#define GROUP_M 8

#define A_BLK_BYTES (TILE_M * 128)              // 32KB per (m_tile, kt64)
#define B_BLK_BYTES (TILE_N * 128)              // 16KB per (n_tile, kt64)
#define STAGE_BYTES (2 * A_BLK_BYTES + 2 * B_BLK_BYTES) // 96KB (K=128)
#define SMEM_DYN (STAGES * STAGE_BYTES)         // 192KB

// ---------------------------------------------------------------------------
// Scratch: pre-converted fp16 operands, TILE-MAJOR + PRE-SWIZZLED.
//   g_xh: [m_tile(32)][kt64(64)] blocks of 256rows x 64k fp16 (32KB),
//         within-block byte off stored at sw128(r*128 + k*2).
//   g_wh: [n_tile(32)][kt64(64)] blocks of 128rows x 64k fp16 (16KB), same.
// Consecutive kt64 blocks are contiguous -> one bulk copy covers K=128.
// ---------------------------------------------------------------------------
__device__ __half g_xh[(size_t)M_TOTAL * K_TOTAL];   // 67 MB
__device__ __half g_wh[(size_t)N_TOTAL * K_TOTAL];   // 33.5 MB

// ---------------------------------------------------------------------------
// Helpers
// ---------------------------------------------------------------------------
__device__ __forceinline__ uint32_t smem_u32(const void* p) {
    uint32_t a;
    asm("{ .reg .u64 t; cvta.to.shared.u64 t, %1; cvt.u32.u64 %0, t; }"
        : "=r"(a) : "l"(p));
    return a;
}

__device__ __forceinline__ uint32_t sw128(uint32_t off) {
    return off ^ ((off >> 3) & 0x70);
}

__device__ __forceinline__ void mbar_init(uint32_t mbar, uint32_t cnt) {
    asm volatile("mbarrier.init.shared::cta.b64 [%0], %1;"
                 :: "r"(mbar), "r"(cnt) : "memory");
}

__device__ __forceinline__ void mbar_expect_tx(uint32_t mbar, uint32_t tx) {
    asm volatile("mbarrier.arrive.expect_tx.shared::cta.b64 _, [%0], %1;"
                 :: "r"(mbar), "r"(tx) : "memory");
}

__device__ __forceinline__ void mbar_wait(uint32_t mbar, uint32_t parity) {
    asm volatile(
        "{\n\t"
        ".reg .pred P;\n\t"
        "WAIT_%=:\n\t"
        "mbarrier.try_wait.parity.acquire.cta.shared::cta.b64 P, [%0], %1, 0x989680;\n\t"
        "@P bra.uni DONE_%=;\n\t"
        "bra.uni WAIT_%=;\n\t"
        "DONE_%=:\n\t"
        "}"
        :: "r"(mbar), "r"(parity) : "memory");
}

__device__ __forceinline__ void bulk_ld(uint32_t dst_smem, const void* src,
                                        uint32_t bytes, uint32_t mbar) {
    asm volatile(
        "cp.async.bulk.shared::cluster.global.mbarrier::complete_tx::bytes "
        "[%0], [%1], %2, [%3];"
        :: "r"(dst_smem), "l"(src), "r"(bytes), "r"(mbar) : "memory");
}

__device__ __forceinline__ void ldsm_x4(uint32_t& r0, uint32_t& r1, uint32_t& r2,
                                        uint32_t& r3, uint32_t addr) {
    asm volatile("ldmatrix.sync.aligned.m8n8.x4.shared.b16 {%0,%1,%2,%3}, [%4];"
                 : "=r"(r0), "=r"(r1), "=r"(r2), "=r"(r3) : "r"(addr));
}

__device__ __forceinline__ void mma16816(float& c0, float& c1, float& c2, float& c3,
                                         uint32_t a0, uint32_t a1, uint32_t a2,
                                         uint32_t a3, uint32_t b0, uint32_t b1) {
    asm volatile(
        "mma.sync.aligned.m16n8k16.row.col.f32.f16.f16.f32 "
        "{%0,%1,%2,%3}, {%4,%5,%6,%7}, {%8,%9}, {%0,%1,%2,%3};"
        : "+f"(c0), "+f"(c1), "+f"(c2), "+f"(c3)
        : "r"(a0), "r"(a1), "r"(a2), "r"(a3), "r"(b0), "r"(b1));
}

// ---------------------------------------------------------------------------
// Pass 1a: convert X (fp32) -> fp16, tile-major pre-swizzled layout.
// Destination is written linearly (chunk i -> byte i*16); source coords are
// recovered via the sw128 involution.
// ---------------------------------------------------------------------------
__global__ void __launch_bounds__(256) cvt_x_kernel(const float* __restrict__ x) {
    size_t i = (size_t)blockIdx.x * blockDim.x + threadIdx.x;   // dst 16B chunk
    size_t n8 = (size_t)M_TOTAL * K_TOTAL / 8;
    if (i >= n8) return;
    uint32_t blk = (uint32_t)(i >> 11);          // 2048 chunks per 32KB block
    uint32_t w = (uint32_t)(i & 2047);
    uint32_t mt = blk >> 6;                      // m_tile
    uint32_t kt = blk & 63;                      // kt64
    uint32_t src_off = sw128(w * 16);            // logical byte off in block
    uint32_t r = src_off >> 7;                   // row 0..255
    uint32_t kc = (src_off & 127) >> 1;          // k within block
    size_t m = (size_t)mt * TILE_M + r;
    size_t k = (size_t)kt * KB64 + kc;
    const float4* s = reinterpret_cast<const float4*>(x + m * K_TOTAL + k);
    float4 a = s[0], b = s[1];
    __half2 h0 = __floats2half2_rn(a.x, a.y);
    __half2 h1 = __floats2half2_rn(a.z, a.w);
    __half2 h2 = __floats2half2_rn(b.x, b.y);
    __half2 h3 = __floats2half2_rn(b.z, b.w);
    uint4 o;
    o.x = reinterpret_cast<uint32_t&>(h0);
    o.y = reinterpret_cast<uint32_t&>(h1);
    o.z = reinterpret_cast<uint32_t&>(h2);
    o.w = reinterpret_cast<uint32_t&>(h3);
    reinterpret_cast<uint4*>(g_xh)[i] = o;
}

// ---------------------------------------------------------------------------
// Pass 1b: dequantize W -> fp16, tile-major pre-swizzled layout.
// flat element e = n*4096+k has scale block e/64 = n*64 + kt.
// ---------------------------------------------------------------------------
__global__ void __launch_bounds__(256) cvt_w_kernel(const int* __restrict__ qw,
                                                    const float* __restrict__ scales) {
    size_t i = (size_t)blockIdx.x * blockDim.x + threadIdx.x;   // dst 16B chunk
    size_t n8 = (size_t)N_TOTAL * K_TOTAL / 8;
    if (i >= n8) return;
    uint32_t blk = (uint32_t)(i >> 10);          // 1024 chunks per 16KB block
    uint32_t w = (uint32_t)(i & 1023);
    uint32_t nt = blk >> 6;                      // n_tile
    uint32_t kt = blk & 63;                      // kt64
    uint32_t src_off = sw128(w * 16);
    uint32_t r = src_off >> 7;                   // row 0..127
    uint32_t kc = (src_off & 127) >> 1;          // k within block
    size_t n = (size_t)nt * TILE_N + r;
    size_t k = (size_t)kt * KB64 + kc;
    float sc = __ldg(scales + (n * 64 + kt));
    const int4* s = reinterpret_cast<const int4*>(qw + n * K_TOTAL + k);
    int4 q0 = s[0], q1 = s[1];
    __half2 h0 = __floats2half2_rn((float)q0.x * sc, (float)q0.y * sc);
    __half2 h1 = __floats2half2_rn((float)q0.z * sc, (float)q0.w * sc);
    __half2 h2 = __floats2half2_rn((float)q1.x * sc, (float)q1.y * sc);
    __half2 h3 = __floats2half2_rn((float)q1.z * sc, (float)q1.w * sc);
    uint4 o;
    o.x = reinterpret_cast<uint32_t&>(h0);
    o.y = reinterpret_cast<uint32_t&>(h1);
    o.z = reinterpret_cast<uint32_t&>(h2);
    o.w = reinterpret_cast<uint32_t&>(h3);
    reinterpret_cast<uint4*>(g_wh)[i] = o;
}

// ---------------------------------------------------------------------------
// Pass 2: HMMA GEMM, 256x128 CTA tile, 16 warps (warp tile 64x32),
//         2-stage K=128 pipeline fed by cp.async.bulk + mbarrier.
//         One mbar_wait + one __syncthreads per 8192 cyc of MMA work.
// ---------------------------------------------------------------------------
__global__ void __launch_bounds__(THREADS, 1) gemm_kernel(const float* __restrict__ bias,
                                                          float* __restrict__ out) {
    extern __shared__ __align__(1024) char smem[];
    __shared__ __align__(8) uint64_t mbars[STAGES];
    uint32_t sb = smem_u32(smem);
    uint32_t mb = smem_u32(mbars);

    int tid = threadIdx.x;
    int wid = tid >> 5;
    int lane = tid & 31;
    int warp_m = wid & 3;        // 4 warps in M (64 rows each)
    int warp_n = wid >> 2;       // 4 warps in N (32 cols each)

    // grouped tile rasterization for L2 reuse
    int bid = blockIdx.x;
    int group = bid / (GROUP_M * N_TILES);
    int rem = bid % (GROUP_M * N_TILES);
    int m_tile = group * GROUP_M + (rem % GROUP_M);
    int n_tile = rem / GROUP_M;

    const char* Ablk = reinterpret_cast<const char*>(g_xh) +
                       (size_t)(m_tile * KTILES64) * A_BLK_BYTES;
    const char* Bblk = reinterpret_cast<const char*>(g_wh) +
                       (size_t)(n_tile * KTILES64) * B_BLK_BYTES;

    if (tid == 0) {
#pragma unroll
        for (int s = 0; s < STAGES; ++s) mbar_init(mb + 8 * s, 1);
    }
    __syncthreads();

    // Stage layout: [A blk 2it][A blk 2it+1][B blk 2it][B blk 2it+1]
    auto load_stage = [&](int it, int buf) {
        uint32_t m = mb + 8 * buf;
        mbar_expect_tx(m, STAGE_BYTES);
        uint32_t stage_base = sb + buf * STAGE_BYTES;
        bulk_ld(stage_base, Ablk + (size_t)(2 * it) * A_BLK_BYTES,
                2 * A_BLK_BYTES, m);                       // 64KB contiguous
        bulk_ld(stage_base + 2 * A_BLK_BYTES,
                Bblk + (size_t)(2 * it) * B_BLK_BYTES,
                2 * B_BLK_BYTES, m);                       // 32KB contiguous
    };

    // prologue: both stages
    if (tid == 0) {
        load_stage(0, 0);
        load_stage(1, 1);
    }

    float acc[4][4][4];
#pragma unroll
    for (int mi = 0; mi < 4; ++mi)
#pragma unroll
        for (int ni = 0; ni < 4; ++ni)
#pragma unroll
            for (int e = 0; e < 4; ++e) acc[mi][ni][e] = 0.0f;

    int lrow = lane & 15;        // row within 16-row block
    int lhalf = lane >> 4;       // which 8-col (k) half

    for (int it = 0; it < ITERS; ++it) {
        int buf = it & 1;
        mbar_wait(mb + 8 * buf, (it >> 1) & 1);
        uint32_t stage_base = sb + buf * STAGE_BYTES;

#pragma unroll
        for (int sub = 0; sub < 2; ++sub) {     // two 64-K sub-blocks
            uint32_t abase = stage_base + sub * A_BLK_BYTES;
            uint32_t bbase = stage_base + 2 * A_BLK_BYTES + sub * B_BLK_BYTES;
#pragma unroll
            for (int ks = 0; ks < 4; ++ks) {    // 4 x k16 per sub-block
                uint32_t a0[4], a1[4], a2[4], a3[4];
#pragma unroll
                for (int mi = 0; mi < 4; ++mi) {
                    int row = warp_m * 64 + mi * 16 + lrow;
                    uint32_t off = (uint32_t)(row * 128 + ks * 32 + lhalf * 16);
                    ldsm_x4(a0[mi], a1[mi], a2[mi], a3[mi], abase + sw128(off));
                }
                uint32_t b0[4], b1[4];
#pragma unroll
                for (int nh = 0; nh < 2; ++nh) {
                    int row = warp_n * 32 + nh * 16 + lrow;
                    uint32_t off = (uint32_t)(row * 128 + ks * 32 + lhalf * 16);
                    uint32_t r0, r1, r2, r3;
                    ldsm_x4(r0, r1, r2, r3, bbase + sw128(off));
                    b0[nh * 2 + 0] = r0; b1[nh * 2 + 0] = r2;
                    b0[nh * 2 + 1] = r1; b1[nh * 2 + 1] = r3;
                }
#pragma unroll
                for (int mi = 0; mi < 4; ++mi)
#pragma unroll
                    for (int ni = 0; ni < 4; ++ni)
                        mma16816(acc[mi][ni][0], acc[mi][ni][1],
                                 acc[mi][ni][2], acc[mi][ni][3],
                                 a0[mi], a1[mi], a2[mi], a3[mi],
                                 b0[ni], b1[ni]);
            }
        }

        // all warps done reading buf -> safe to re-target with TMA
        __syncthreads();
        if (tid == 0 && it + 2 < ITERS) load_stage(it + 2, buf);
    }

    // epilogue: bias add + store
    int m_base = m_tile * TILE_M;
    int n_base = n_tile * TILE_N;
    int qr = lane >> 2;          // 0..7
    int qc = (lane & 3) * 2;     // 0,2,4,6
#pragma unroll
    for (int mi = 0; mi < 4; ++mi) {
        int row0 = m_base + warp_m * 64 + mi * 16 + qr;
#pragma unroll
        for (int ni = 0; ni < 4; ++ni) {
            int col = n_base + warp_n * 32 + ni * 8 + qc;
            float bx = __ldg(bias + col);
            float by = __ldg(bias + col + 1);
            float2 v0 = make_float2(acc[mi][ni][0] + bx, acc[mi][ni][1] + by);
            float2 v1 = make_float2(acc[mi][ni][2] + bx, acc[mi][ni][3] + by);
            *reinterpret_cast<float2*>(out + (size_t)row0 * N_TOTAL + col) = v0;
            *reinterpret_cast<float2*>(out + (size_t)(row0 + 8) * N_TOTAL + col) = v1;
        }
    }
}

// ---------------------------------------------------------------------------
// kernel_launch
// ---------------------------------------------------------------------------
extern "C" void kernel_launch(void* const* d_in, const int* in_sizes, int n_in,
                              void* d_out, int out_size) {
    const float* x      = (const float*)d_in[0];
    const int*   qw     = (const int*)d_in[1];
    const float* scales = (const float*)d_in[2];
    const float* bias   = (const float*)d_in[3];
    float*       out    = (float*)d_out;

    cudaFuncSetAttribute(gemm_kernel, cudaFuncAttributeMaxDynamicSharedMemorySize, SMEM_DYN);

    int n8x = (int)((size_t)M_TOTAL * K_TOTAL / 8);   // 4,194,304
    int n8w = (int)((size_t)N_TOTAL * K_TOTAL / 8);   // 2,097,152
    cvt_x_kernel<<<(n8x + 255) / 256, 256>>>(x);
    cvt_w_kernel<<<(n8w + 255) / 256, 256>>>(qw, scales);
    gemm_kernel<<<M_TILES * N_TILES, THREADS, SMEM_DYN>>>(bias, out);
}

// round 7
// speedup vs baseline: 1.1516x; 1.0675x over previous
#include <cuda_runtime.h>
#include <cuda_fp16.h>
#include <cstdint>

// ---------------------------------------------------------------------------
// Problem constants
// ---------------------------------------------------------------------------
#define M_TOTAL 8192
#define N_TOTAL 4096
#define K_TOTAL 4096

#define TILE_M 256
#define TILE_N 128
#define KB64 64                      // granularity of pre-packed blocks
#define KTILES64 (K_TOTAL / KB64)    // 64 blocks in K
#define ITERS (KTILES64 / 2)         // 32 mainloop iterations (K=128 each)
#define STAGES 2
#define THREADS 256                  // 8 warps, warp tile 64x64
#define N_TILES (N_TOTAL / TILE_N)   // 32
#define M_TILES (M_TOTAL / TILE_M)   // 32
#define TOTAL_TILES (M_TILES * N_TILES)  // 1024
#define GROUP_M 8
#define GRID 148                     // persistent CTAs

#define A_BLK_BYTES (TILE_M * 128)              // 32KB per (m_tile, kt64)
#define B_BLK_BYTES (TILE_N * 128)              // 16KB per (n_tile, kt64)
#define STAGE_BYTES (2 * A_BLK_BYTES + 2 * B_BLK_BYTES) // 96KB (K=128)
#define SMEM_DYN (STAGES * STAGE_BYTES)         // 192KB

// ---------------------------------------------------------------------------
// Scratch: pre-converted fp16 operands, TILE-MAJOR + PRE-SWIZZLED.
//   g_xh: [m_tile(32)][kt64(64)] blocks of 256rows x 64k fp16 (32KB),
//         within-block byte off stored at sw128(r*128 + k*2).
//   g_wh: [n_tile(32)][kt64(64)] blocks of 128rows x 64k fp16 (16KB), same.
// Consecutive kt64 blocks are contiguous -> one bulk copy covers K=128.
// ---------------------------------------------------------------------------
__device__ __half g_xh[(size_t)M_TOTAL * K_TOTAL];   // 67 MB
__device__ __half g_wh[(size_t)N_TOTAL * K_TOTAL];   // 33.5 MB

// ---------------------------------------------------------------------------
// Helpers
// ---------------------------------------------------------------------------
__device__ __forceinline__ uint32_t smem_u32(const void* p) {
    uint32_t a;
    asm("{ .reg .u64 t; cvta.to.shared.u64 t, %1; cvt.u32.u64 %0, t; }"
        : "=r"(a) : "l"(p));
    return a;
}

__device__ __forceinline__ uint32_t sw128(uint32_t off) {
    return off ^ ((off >> 3) & 0x70);
}

__device__ __forceinline__ void mbar_init(uint32_t mbar, uint32_t cnt) {
    asm volatile("mbarrier.init.shared::cta.b64 [%0], %1;"
                 :: "r"(mbar), "r"(cnt) : "memory");
}

__device__ __forceinline__ void mbar_expect_tx(uint32_t mbar, uint32_t tx) {
    asm volatile("mbarrier.arrive.expect_tx.shared::cta.b64 _, [%0], %1;"
                 :: "r"(mbar), "r"(tx) : "memory");
}

__device__ __forceinline__ void mbar_wait(uint32_t mbar, uint32_t parity) {
    asm volatile(
        "{\n\t"
        ".reg .pred P;\n\t"
        "WAIT_%=:\n\t"
        "mbarrier.try_wait.parity.acquire.cta.shared::cta.b64 P, [%0], %1, 0x989680;\n\t"
        "@P bra.uni DONE_%=;\n\t"
        "bra.uni WAIT_%=;\n\t"
        "DONE_%=:\n\t"
        "}"
        :: "r"(mbar), "r"(parity) : "memory");
}

__device__ __forceinline__ void bulk_ld(uint32_t dst_smem, const void* src,
                                        uint32_t bytes, uint32_t mbar) {
    asm volatile(
        "cp.async.bulk.shared::cluster.global.mbarrier::complete_tx::bytes "
        "[%0], [%1], %2, [%3];"
        :: "r"(dst_smem), "l"(src), "r"(bytes), "r"(mbar) : "memory");
}

__device__ __forceinline__ void ldsm_x4(uint32_t& r0, uint32_t& r1, uint32_t& r2,
                                        uint32_t& r3, uint32_t addr) {
    asm volatile("ldmatrix.sync.aligned.m8n8.x4.shared.b16 {%0,%1,%2,%3}, [%4];"
                 : "=r"(r0), "=r"(r1), "=r"(r2), "=r"(r3) : "r"(addr));
}

__device__ __forceinline__ void mma16816(float& c0, float& c1, float& c2, float& c3,
                                         uint32_t a0, uint32_t a1, uint32_t a2,
                                         uint32_t a3, uint32_t b0, uint32_t b1) {
    asm volatile(
        "mma.sync.aligned.m16n8k16.row.col.f32.f16.f16.f32 "
        "{%0,%1,%2,%3}, {%4,%5,%6,%7}, {%8,%9}, {%0,%1,%2,%3};"
        : "+f"(c0), "+f"(c1), "+f"(c2), "+f"(c3)
        : "r"(a0), "r"(a1), "r"(a2), "r"(a3), "r"(b0), "r"(b1));
}

// ---------------------------------------------------------------------------
// Pass 1a: convert X (fp32) -> fp16, tile-major pre-swizzled layout.
// ---------------------------------------------------------------------------
__global__ void __launch_bounds__(256) cvt_x_kernel(const float* __restrict__ x) {
    size_t i = (size_t)blockIdx.x * blockDim.x + threadIdx.x;   // dst 16B chunk
    size_t n8 = (size_t)M_TOTAL * K_TOTAL / 8;
    if (i >= n8) return;
    uint32_t blk = (uint32_t)(i >> 11);          // 2048 chunks per 32KB block
    uint32_t w = (uint32_t)(i & 2047);
    uint32_t mt = blk >> 6;                      // m_tile
    uint32_t kt = blk & 63;                      // kt64
    uint32_t src_off = sw128(w * 16);            // logical byte off in block
    uint32_t r = src_off >> 7;                   // row 0..255
    uint32_t kc = (src_off & 127) >> 1;          // k within block
    size_t m = (size_t)mt * TILE_M + r;
    size_t k = (size_t)kt * KB64 + kc;
    const float4* s = reinterpret_cast<const float4*>(x + m * K_TOTAL + k);
    float4 a = s[0], b = s[1];
    __half2 h0 = __floats2half2_rn(a.x, a.y);
    __half2 h1 = __floats2half2_rn(a.z, a.w);
    __half2 h2 = __floats2half2_rn(b.x, b.y);
    __half2 h3 = __floats2half2_rn(b.z, b.w);
    uint4 o;
    o.x = reinterpret_cast<uint32_t&>(h0);
    o.y = reinterpret_cast<uint32_t&>(h1);
    o.z = reinterpret_cast<uint32_t&>(h2);
    o.w = reinterpret_cast<uint32_t&>(h3);
    reinterpret_cast<uint4*>(g_xh)[i] = o;
}

// ---------------------------------------------------------------------------
// Pass 1b: dequantize W -> fp16, tile-major pre-swizzled layout.
// ---------------------------------------------------------------------------
__global__ void __launch_bounds__(256) cvt_w_kernel(const int* __restrict__ qw,
                                                    const float* __restrict__ scales) {
    size_t i = (size_t)blockIdx.x * blockDim.x + threadIdx.x;   // dst 16B chunk
    size_t n8 = (size_t)N_TOTAL * K_TOTAL / 8;
    if (i >= n8) return;
    uint32_t blk = (uint32_t)(i >> 10);          // 1024 chunks per 16KB block
    uint32_t w = (uint32_t)(i & 1023);
    uint32_t nt = blk >> 6;                      // n_tile
    uint32_t kt = blk & 63;                      // kt64
    uint32_t src_off = sw128(w * 16);
    uint32_t r = src_off >> 7;                   // row 0..127
    uint32_t kc = (src_off & 127) >> 1;          // k within block
    size_t n = (size_t)nt * TILE_N + r;
    size_t k = (size_t)kt * KB64 + kc;
    float sc = __ldg(scales + (n * 64 + kt));
    const int4* s = reinterpret_cast<const int4*>(qw + n * K_TOTAL + k);
    int4 q0 = s[0], q1 = s[1];
    __half2 h0 = __floats2half2_rn((float)q0.x * sc, (float)q0.y * sc);
    __half2 h1 = __floats2half2_rn((float)q0.z * sc, (float)q0.w * sc);
    __half2 h2 = __floats2half2_rn((float)q1.x * sc, (float)q1.y * sc);
    __half2 h3 = __floats2half2_rn((float)q1.z * sc, (float)q1.w * sc);
    uint4 o;
    o.x = reinterpret_cast<uint32_t&>(h0);
    o.y = reinterpret_cast<uint32_t&>(h1);
    o.z = reinterpret_cast<uint32_t&>(h2);
    o.w = reinterpret_cast<uint32_t&>(h3);
    reinterpret_cast<uint4*>(g_wh)[i] = o;
}

// ---------------------------------------------------------------------------
// Pass 2: persistent HMMA GEMM.
//   CTA tile 256x128, 8 warps (warp tile 64x64), 2-stage K=128 TMA pipeline.
//   Persistent grid=148; TMA for tile t+GRID issued during tile t's tail,
//   so next-tile loads overlap this tile's epilogue stores.
// ---------------------------------------------------------------------------
__global__ void __launch_bounds__(THREADS, 1) gemm_kernel(const float* __restrict__ bias,
                                                          float* __restrict__ out) {
    extern __shared__ __align__(1024) char smem[];
    __shared__ __align__(8) uint64_t mbars[STAGES];
    uint32_t sb = smem_u32(smem);
    uint32_t mb = smem_u32(mbars);

    int tid = threadIdx.x;
    int wid = tid >> 5;          // 0..7
    int lane = tid & 31;
    int warp_m = wid & 3;        // 4 warps in M (64 rows each)
    int warp_n = wid >> 2;       // 2 warps in N (64 cols each)

    if (tid == 0) {
#pragma unroll
        for (int s = 0; s < STAGES; ++s) mbar_init(mb + 8 * s, 1);
    }
    __syncthreads();

    auto tile_ptrs = [&](int t, const char*& Ab, const char*& Bb, int& mt, int& nt) {
        int group = t / (GROUP_M * N_TILES);
        int rem = t % (GROUP_M * N_TILES);
        mt = group * GROUP_M + (rem % GROUP_M);
        nt = rem / GROUP_M;
        Ab = reinterpret_cast<const char*>(g_xh) + (size_t)(mt * KTILES64) * A_BLK_BYTES;
        Bb = reinterpret_cast<const char*>(g_wh) + (size_t)(nt * KTILES64) * B_BLK_BYTES;
    };

    // issue one K=128 stage (2 contiguous 64-blocks of A and B)
    auto load_stage = [&](const char* Ab, const char* Bb, int it, uint32_t g) {
        uint32_t buf = g & 1;
        uint32_t m = mb + 8 * buf;
        mbar_expect_tx(m, STAGE_BYTES);
        uint32_t stage_base = sb + buf * STAGE_BYTES;
        bulk_ld(stage_base, Ab + (size_t)(2 * it) * A_BLK_BYTES, 2 * A_BLK_BYTES, m);
        bulk_ld(stage_base + 2 * A_BLK_BYTES, Bb + (size_t)(2 * it) * B_BLK_BYTES,
                2 * B_BLK_BYTES, m);
    };

    int lrow = lane & 15;        // row within 16-row block
    int lhalf = lane >> 4;       // which 8-col (k) half
    int qr = lane >> 2;          // 0..7 (epilogue)
    int qc = (lane & 3) * 2;     // 0,2,4,6 (epilogue)

    uint32_t g = 0;              // global stage counter (buf = g&1, parity = (g>>1)&1)

    for (int t = blockIdx.x; t < TOTAL_TILES; t += GRID) {
        const char *A0, *B0, *A1 = nullptr, *B1 = nullptr;
        int m_tile, n_tile, mt1, nt1;
        tile_ptrs(t, A0, B0, m_tile, n_tile);
        bool has_next = (t + GRID < TOTAL_TILES);
        if (has_next) tile_ptrs(t + GRID, A1, B1, mt1, nt1);

        if (t == (int)blockIdx.x && tid == 0) {   // prologue, first tile only
            load_stage(A0, B0, 0, g);
            load_stage(A0, B0, 1, g + 1);
        }

        float acc[4][8][4];
#pragma unroll
        for (int mi = 0; mi < 4; ++mi)
#pragma unroll
            for (int ni = 0; ni < 8; ++ni)
#pragma unroll
                for (int e = 0; e < 4; ++e) acc[mi][ni][e] = 0.0f;

        for (int it = 0; it < ITERS; ++it) {
            uint32_t buf = g & 1;
            mbar_wait(mb + 8 * buf, (g >> 1) & 1);
            uint32_t stage_base = sb + buf * STAGE_BYTES;

#pragma unroll
            for (int sub = 0; sub < 2; ++sub) {     // two 64-K sub-blocks
                uint32_t abase = stage_base + sub * A_BLK_BYTES;
                uint32_t bbase = stage_base + 2 * A_BLK_BYTES + sub * B_BLK_BYTES;
#pragma unroll
                for (int ks = 0; ks < 4; ++ks) {    // 4 x k16 per sub-block
                    uint32_t a0[4], a1[4], a2[4], a3[4];
#pragma unroll
                    for (int mi = 0; mi < 4; ++mi) {
                        int row = warp_m * 64 + mi * 16 + lrow;
                        uint32_t off = (uint32_t)(row * 128 + ks * 32 + lhalf * 16);
                        ldsm_x4(a0[mi], a1[mi], a2[mi], a3[mi], abase + sw128(off));
                    }
                    uint32_t b0[8], b1[8];
#pragma unroll
                    for (int nh = 0; nh < 4; ++nh) {
                        int row = warp_n * 64 + nh * 16 + lrow;
                        uint32_t off = (uint32_t)(row * 128 + ks * 32 + lhalf * 16);
                        uint32_t r0, r1, r2, r3;
                        ldsm_x4(r0, r1, r2, r3, bbase + sw128(off));
                        b0[nh * 2 + 0] = r0; b1[nh * 2 + 0] = r2;
                        b0[nh * 2 + 1] = r1; b1[nh * 2 + 1] = r3;
                    }
#pragma unroll
                    for (int mi = 0; mi < 4; ++mi)
#pragma unroll
                        for (int ni = 0; ni < 8; ++ni)
                            mma16816(acc[mi][ni][0], acc[mi][ni][1],
                                     acc[mi][ni][2], acc[mi][ni][3],
                                     a0[mi], a1[mi], a2[mi], a3[mi],
                                     b0[ni], b1[ni]);
                }
            }

            // all warps done reading buf -> safe to re-target with TMA
            __syncthreads();
            if (tid == 0) {
                int nx = it + 2;
                if (nx < ITERS) load_stage(A0, B0, nx, g);           // same buf as g
                else if (has_next) load_stage(A1, B1, nx - ITERS, g); // next tile's stage
            }
            ++g;
        }

        // epilogue: bias add + store (next tile's TMA already in flight)
        int m_base = m_tile * TILE_M;
        int n_base = n_tile * TILE_N;
#pragma unroll
        for (int mi = 0; mi < 4; ++mi) {
            int row0 = m_base + warp_m * 64 + mi * 16 + qr;
#pragma unroll
            for (int ni = 0; ni < 8; ++ni) {
                int col = n_base + warp_n * 64 + ni * 8 + qc;
                float bx = __ldg(bias + col);
                float by = __ldg(bias + col + 1);
                float2 v0 = make_float2(acc[mi][ni][0] + bx, acc[mi][ni][1] + by);
                float2 v1 = make_float2(acc[mi][ni][2] + bx, acc[mi][ni][3] + by);
                *reinterpret_cast<float2*>(out + (size_t)row0 * N_TOTAL + col) = v0;
                *reinterpret_cast<float2*>(out + (size_t)(row0 + 8) * N_TOTAL + col) = v1;
            }
        }
    }
}

// ---------------------------------------------------------------------------
// kernel_launch
// ---------------------------------------------------------------------------
extern "C" void kernel_launch(void* const* d_in, const int* in_sizes, int n_in,
                              void* d_out, int out_size) {
    const float* x      = (const float*)d_in[0];
    const int*   qw     = (const int*)d_in[1];
    const float* scales = (const float*)d_in[2];
    const float* bias   = (const float*)d_in[3];
    float*       out    = (float*)d_out;

    cudaFuncSetAttribute(gemm_kernel, cudaFuncAttributeMaxDynamicSharedMemorySize, SMEM_DYN);

    int n8x = (int)((size_t)M_TOTAL * K_TOTAL / 8);   // 4,194,304
    int n8w = (int)((size_t)N_TOTAL * K_TOTAL / 8);   // 2,097,152
    cvt_x_kernel<<<(n8x + 255) / 256, 256>>>(x);
    cvt_w_kernel<<<(n8w + 255) / 256, 256>>>(qw, scales);
    gemm_kernel<<<GRID, THREADS, SMEM_DYN>>>(bias, out);
}